// round 2
// baseline (speedup 1.0000x reference)
#include <cuda_runtime.h>

// ---------------------------------------------------------------------------
// ViT patch-embed + QKV + attention, fp32 baseline (round 1)
//   x[8,3,448,448] --patchify--> patches[8192,588]
//   tokens = patches @ conv_w^T + conv_b           (GEMM1, 8192x588x588)
//   qkv    = tokens  @ qkv_w^T  + qkv_b            (GEMM2, 8192x1764x588)
//     scattered into qT[B,H,42,1024], kT[B,H,42,1024], v[B,H,1024,42]
//   out[b,n,h*42+d] = flash-attention per (b,h)
// ---------------------------------------------------------------------------

namespace {
constexpr int B_    = 8;
constexpr int NTOK  = 1024;   // 32*32 patches
constexpr int CDIM  = 588;
constexpr int NH    = 14;
constexpr int HD    = 42;
constexpr int MTOT  = B_ * NTOK;     // 8192
constexpr int QKVN  = 3 * CDIM;      // 1764
constexpr float ATTN_SCALE = 0.125f;
}

__device__ float g_patches[MTOT * CDIM];
__device__ float g_tokens [MTOT * CDIM];
__device__ float g_qT[B_ * NH * HD * NTOK];
__device__ float g_kT[B_ * NH * HD * NTOK];
__device__ float g_v [B_ * NH * NTOK * HD];

// ---------------------------------------------------------------------------
// Patchify: patches[m][k], m = b*1024 + py*32 + px, k = c*196 + i*14 + j
// ---------------------------------------------------------------------------
__global__ __launch_bounds__(256) void patch_extract_k(const float* __restrict__ x) {
    int idx = blockIdx.x * 256 + threadIdx.x;
    if (idx >= MTOT * CDIM) return;
    int m = idx / CDIM;
    int k = idx - m * CDIM;
    int c  = k / 196;
    int r2 = k - c * 196;
    int i  = r2 / 14;
    int j  = r2 - i * 14;
    int b  = m >> 10;
    int sp = m & 1023;
    int py = sp >> 5;
    int px = sp & 31;
    g_patches[idx] = x[((size_t)(b * 3 + c) * 448 + py * 14 + i) * 448 + (px * 14 + j)];
}

// ---------------------------------------------------------------------------
// GEMM1: g_tokens[M,588] = g_patches[M,588] @ W[588,588]^T + bias
// BM=BN=64, BK=16, 256 threads, 4x4 micro-tile
// ---------------------------------------------------------------------------
__global__ __launch_bounds__(256) void gemm1_k(const float* __restrict__ W,
                                               const float* __restrict__ bias) {
    const int K = CDIM, N = CDIM;
    __shared__ float As[16][68];
    __shared__ float Bs[16][68];
    int tid = threadIdx.x;
    int ty = tid >> 4, tx = tid & 15;
    int m0 = blockIdx.y << 6, n0 = blockIdx.x << 6;
    int lrow = tid >> 2;
    int lk   = (tid & 3) << 2;
    bool brow_ok = (n0 + lrow) < N;

    const float* Ap = g_patches + (size_t)(m0 + lrow) * K + lk;
    const float* Bp = W         + (size_t)(n0 + lrow) * K + lk;

    float acc[4][4] = {};
    for (int k0 = 0; k0 < K; k0 += 16) {
        float4 av = make_float4(0.f, 0.f, 0.f, 0.f);
        float4 bv = av;
        if (k0 + lk < K) {
            av = *(const float4*)(Ap + k0);
            if (brow_ok) bv = *(const float4*)(Bp + k0);
        }
        As[lk + 0][lrow] = av.x; As[lk + 1][lrow] = av.y;
        As[lk + 2][lrow] = av.z; As[lk + 3][lrow] = av.w;
        Bs[lk + 0][lrow] = bv.x; Bs[lk + 1][lrow] = bv.y;
        Bs[lk + 2][lrow] = bv.z; Bs[lk + 3][lrow] = bv.w;
        __syncthreads();
        #pragma unroll
        for (int kk = 0; kk < 16; kk++) {
            float4 a = *(const float4*)&As[kk][ty << 2];
            float4 b = *(const float4*)&Bs[kk][tx << 2];
            float a4[4] = {a.x, a.y, a.z, a.w};
            float b4[4] = {b.x, b.y, b.z, b.w};
            #pragma unroll
            for (int i = 0; i < 4; i++)
                #pragma unroll
                for (int j = 0; j < 4; j++)
                    acc[i][j] += a4[i] * b4[j];
        }
        __syncthreads();
    }
    #pragma unroll
    for (int i = 0; i < 4; i++) {
        int m = m0 + (ty << 2) + i;
        #pragma unroll
        for (int j = 0; j < 4; j++) {
            int n = n0 + (tx << 2) + j;
            if (n < N) g_tokens[(size_t)m * N + n] = acc[i][j] + bias[n];
        }
    }
}

// ---------------------------------------------------------------------------
// GEMM2: qkv = g_tokens[M,588] @ W[1764,588]^T + bias, scattered into
//   qT[(b*14+h)*42+d][1024] , kT same , v[(b*14+h)*1024+n][42]
// ---------------------------------------------------------------------------
__global__ __launch_bounds__(256) void gemm2_k(const float* __restrict__ W,
                                               const float* __restrict__ bias) {
    const int K = CDIM, N = QKVN;
    __shared__ float As[16][68];
    __shared__ float Bs[16][68];
    int tid = threadIdx.x;
    int ty = tid >> 4, tx = tid & 15;
    int m0 = blockIdx.y << 6, n0 = blockIdx.x << 6;
    int lrow = tid >> 2;
    int lk   = (tid & 3) << 2;
    bool brow_ok = (n0 + lrow) < N;

    const float* Ap = g_tokens + (size_t)(m0 + lrow) * K + lk;
    const float* Bp = W        + (size_t)(n0 + lrow) * K + lk;

    float acc[4][4] = {};
    for (int k0 = 0; k0 < K; k0 += 16) {
        float4 av = make_float4(0.f, 0.f, 0.f, 0.f);
        float4 bv = av;
        if (k0 + lk < K) {
            av = *(const float4*)(Ap + k0);
            if (brow_ok) bv = *(const float4*)(Bp + k0);
        }
        As[lk + 0][lrow] = av.x; As[lk + 1][lrow] = av.y;
        As[lk + 2][lrow] = av.z; As[lk + 3][lrow] = av.w;
        Bs[lk + 0][lrow] = bv.x; Bs[lk + 1][lrow] = bv.y;
        Bs[lk + 2][lrow] = bv.z; Bs[lk + 3][lrow] = bv.w;
        __syncthreads();
        #pragma unroll
        for (int kk = 0; kk < 16; kk++) {
            float4 a = *(const float4*)&As[kk][ty << 2];
            float4 b = *(const float4*)&Bs[kk][tx << 2];
            float a4[4] = {a.x, a.y, a.z, a.w};
            float b4[4] = {b.x, b.y, b.z, b.w};
            #pragma unroll
            for (int i = 0; i < 4; i++)
                #pragma unroll
                for (int j = 0; j < 4; j++)
                    acc[i][j] += a4[i] * b4[j];
        }
        __syncthreads();
    }
    #pragma unroll
    for (int i = 0; i < 4; i++) {
        int m = m0 + (ty << 2) + i;
        int b = m >> 10, n = m & 1023;
        #pragma unroll
        for (int j = 0; j < 4; j++) {
            int o = n0 + (tx << 2) + j;
            if (o < N) {
                float val = acc[i][j] + bias[o];
                int sgrp = o / CDIM;          // 0=q 1=k 2=v
                int cc   = o - sgrp * CDIM;
                int h    = cc / HD;
                int d    = cc - h * HD;
                int bh   = b * NH + h;
                if (sgrp == 0)      g_qT[((size_t)bh * HD + d) * NTOK + n] = val;
                else if (sgrp == 1) g_kT[((size_t)bh * HD + d) * NTOK + n] = val;
                else                g_v [((size_t)bh * NTOK + n) * HD + d] = val;
            }
        }
    }
}

// ---------------------------------------------------------------------------
// Flash attention per (b,h): BR=64 q-rows per CTA, 16 KV tiles of 64.
// Qs[d][r], K and P share one smem buffer (sync-separated), Vs[c][d(48)].
// 256 threads, 16x16 grid; scores 4x4 per thread, output 4 rows x 3 dims.
// ---------------------------------------------------------------------------
__global__ __launch_bounds__(256) void attn_k(float* __restrict__ out) {
    __shared__ float Qs[HD * 64];   // [d][r]  stride 64
    __shared__ float KP[64 * 64];   // phase 1: K [d][c] stride 64; phase 2: P [r][c] stride 64
    __shared__ float Vs[64 * 48];   // [c][d]  stride 48 (d 42..47 zero)

    int tid = threadIdx.x;
    int ty = tid >> 4, tx = tid & 15;
    int bh = blockIdx.y;
    int r0 = blockIdx.x << 6;

    const float* qb = g_qT + (size_t)bh * HD * NTOK + r0;
    const float* kb = g_kT + (size_t)bh * HD * NTOK;
    const float* vb = g_v  + (size_t)bh * NTOK * HD;

    for (int idx = tid; idx < HD * 64; idx += 256) {
        int d = idx >> 6, r = idx & 63;
        Qs[idx] = qb[(size_t)d * NTOK + r];
    }

    float m_run[4], l_run[4], o_acc[4][3];
    #pragma unroll
    for (int i = 0; i < 4; i++) {
        m_run[i] = -1e30f;
        l_run[i] = 0.f;
        o_acc[i][0] = o_acc[i][1] = o_acc[i][2] = 0.f;
    }

    for (int c0 = 0; c0 < NTOK; c0 += 64) {
        // load K tile (transposed layout comes free from kT) and V tile
        for (int idx = tid; idx < HD * 64; idx += 256) {
            int d = idx >> 6, c = idx & 63;
            KP[idx] = kb[(size_t)d * NTOK + c0 + c];
        }
        for (int idx = tid; idx < 64 * 48; idx += 256) {
            int c = idx / 48, d = idx - c * 48;
            Vs[idx] = (d < HD) ? vb[(size_t)(c0 + c) * HD + d] : 0.f;
        }
        __syncthreads();

        // S = Q K^T
        float s[4][4] = {};
        #pragma unroll
        for (int d = 0; d < HD; d++) {
            float4 a = *(const float4*)&Qs[d * 64 + (ty << 2)];
            float4 b = *(const float4*)&KP[d * 64 + (tx << 2)];
            float a4[4] = {a.x, a.y, a.z, a.w};
            float b4[4] = {b.x, b.y, b.z, b.w};
            #pragma unroll
            for (int i = 0; i < 4; i++)
                #pragma unroll
                for (int j = 0; j < 4; j++)
                    s[i][j] += a4[i] * b4[j];
        }
        __syncthreads();   // everyone done reading KP as K before P overwrites it

        // online softmax (row groups span the 16 tx lanes = one half-warp)
        #pragma unroll
        for (int i = 0; i < 4; i++) {
            float mt = -1e30f;
            #pragma unroll
            for (int j = 0; j < 4; j++) {
                s[i][j] *= ATTN_SCALE;
                mt = fmaxf(mt, s[i][j]);
            }
            #pragma unroll
            for (int off = 1; off < 16; off <<= 1)
                mt = fmaxf(mt, __shfl_xor_sync(0xffffffffu, mt, off));
            float m_new = fmaxf(m_run[i], mt);
            float lt = 0.f;
            #pragma unroll
            for (int j = 0; j < 4; j++) {
                s[i][j] = __expf(s[i][j] - m_new);
                lt += s[i][j];
            }
            #pragma unroll
            for (int off = 1; off < 16; off <<= 1)
                lt += __shfl_xor_sync(0xffffffffu, lt, off);
            float alpha = __expf(m_run[i] - m_new);
            m_run[i] = m_new;
            l_run[i] = l_run[i] * alpha + lt;
            o_acc[i][0] *= alpha; o_acc[i][1] *= alpha; o_acc[i][2] *= alpha;
            *(float4*)&KP[(((ty << 2) + i) << 6) + (tx << 2)] =
                make_float4(s[i][0], s[i][1], s[i][2], s[i][3]);
        }
        __syncthreads();

        // O += P V
        #pragma unroll 8
        for (int c = 0; c < 64; c++) {
            float v0 = Vs[c * 48 + tx * 3 + 0];
            float v1 = Vs[c * 48 + tx * 3 + 1];
            float v2 = Vs[c * 48 + tx * 3 + 2];
            #pragma unroll
            for (int i = 0; i < 4; i++) {
                float p = KP[(((ty << 2) + i) << 6) + c];
                o_acc[i][0] += p * v0;
                o_acc[i][1] += p * v1;
                o_acc[i][2] += p * v2;
            }
        }
        __syncthreads();
    }

    int b = bh / NH, h = bh - b * NH;
    #pragma unroll
    for (int i = 0; i < 4; i++) {
        int n = r0 + (ty << 2) + i;
        float inv = 1.f / l_run[i];
        #pragma unroll
        for (int jj = 0; jj < 3; jj++) {
            int d = tx * 3 + jj;
            if (d < HD)
                out[((size_t)(b * NTOK + n)) * CDIM + h * HD + d] = o_acc[i][jj] * inv;
        }
    }
}

// ---------------------------------------------------------------------------
extern "C" void kernel_launch(void* const* d_in, const int* in_sizes, int n_in,
                              void* d_out, int out_size) {
    const float* x      = (const float*)d_in[0];
    const float* conv_w = (const float*)d_in[1];
    const float* conv_b = (const float*)d_in[2];
    const float* qkv_w  = (const float*)d_in[3];
    const float* qkv_b  = (const float*)d_in[4];
    float* out = (float*)d_out;

    patch_extract_k<<<(MTOT * CDIM + 255) / 256, 256>>>(x);
    gemm1_k<<<dim3((CDIM + 63) / 64, MTOT / 64), 256>>>(conv_w, conv_b);
    gemm2_k<<<dim3((QKVN + 63) / 64, MTOT / 64), 256>>>(qkv_w, qkv_b);
    attn_k<<<dim3(NTOK / 64, B_ * NH), 256>>>(out);
}

// round 5
// speedup vs baseline: 1.0905x; 1.0905x over previous
#include <cuda_runtime.h>

// ---------------------------------------------------------------------------
// ViT patch-embed + QKV + attention, fp32 (round 4)
//  - GEMMs: 128x128x8 tiles, 8x8 split micro-tile; A source selected in
//    DEVICE code (R3 bug: __device__ global passed as kernel arg from host)
//  - attention: conflict-free float4 PV (stride 68), stats in registers
// ---------------------------------------------------------------------------

namespace {
constexpr int B_    = 8;
constexpr int NTOK  = 1024;
constexpr int CDIM  = 588;
constexpr int NH    = 14;
constexpr int HD    = 42;
constexpr int MTOT  = B_ * NTOK;     // 8192
constexpr int QKVN  = 3 * CDIM;      // 1764
constexpr float ATTN_SCALE = 0.125f;
constexpr int KSTR  = 68;            // attn smem row stride (words, mult of 4)
}

__device__ float g_patches[MTOT * CDIM];
__device__ float g_tokens [MTOT * CDIM];
__device__ float g_qT[B_ * NH * HD * NTOK];
__device__ float g_kT[B_ * NH * HD * NTOK];
__device__ float g_vT[B_ * NH * HD * NTOK];

// ---------------------------------------------------------------------------
// Patchify: patches[m][k], m = b*1024 + py*32 + px, k = c*196 + i*14 + j
// ---------------------------------------------------------------------------
__global__ __launch_bounds__(256) void patch_extract_k(const float* __restrict__ x) {
    int idx = blockIdx.x * 256 + threadIdx.x;
    if (idx >= MTOT * CDIM) return;
    int m = idx / CDIM;
    int k = idx - m * CDIM;
    int c  = k / 196;
    int r2 = k - c * 196;
    int i  = r2 / 14;
    int j  = r2 - i * 14;
    int b  = m >> 10;
    int sp = m & 1023;
    int py = sp >> 5;
    int px = sp & 31;
    g_patches[idx] = x[((size_t)(b * 3 + c) * 448 + py * 14 + i) * 448 + (px * 14 + j)];
}

// ---------------------------------------------------------------------------
// GEMM: C[M, NCOLS] = A[M,588] @ W[NCOLS,588]^T + bias
// 128x128x8 tile, 256 threads, 8x8 per thread in 4 quadrants of 4x4.
// SCATTER=false: A = g_patches, write g_tokens.
// SCATTER=true : A = g_tokens,  scatter into qT/kT/vT.
// ---------------------------------------------------------------------------
template<int NCOLS, bool SCATTER>
__global__ __launch_bounds__(256) void gemm_k(const float* __restrict__ W,
                                              const float* __restrict__ bias) {
    constexpr int K = CDIM;
    __shared__ float As[8][132];
    __shared__ float Bs[8][132];

    const float* __restrict__ A = SCATTER ? g_tokens : g_patches;

    int tid = threadIdx.x;
    int ty = tid >> 4, tx = tid & 15;          // micro-tile coords
    int m0 = blockIdx.y << 7, n0 = blockIdx.x << 7;

    int lrow = tid >> 1;                        // 0..127
    int lk   = (tid & 1) << 2;                  // 0 or 4
    bool brow_ok = (n0 + lrow) < NCOLS;

    const float* Ap = A + (size_t)(m0 + lrow) * K + lk;
    const float* Bp = W + (size_t)(n0 + lrow) * K + lk;

    float acc[8][8] = {};

    for (int k0 = 0; k0 < K; k0 += 8) {
        float4 av = make_float4(0.f, 0.f, 0.f, 0.f);
        float4 bv = av;
        if (k0 + lk < K) {                      // K%4==0 so full float4 valid
            av = *(const float4*)(Ap + k0);
            if (brow_ok) bv = *(const float4*)(Bp + k0);
        }
        As[lk + 0][lrow] = av.x; As[lk + 1][lrow] = av.y;
        As[lk + 2][lrow] = av.z; As[lk + 3][lrow] = av.w;
        Bs[lk + 0][lrow] = bv.x; Bs[lk + 1][lrow] = bv.y;
        Bs[lk + 2][lrow] = bv.z; Bs[lk + 3][lrow] = bv.w;
        __syncthreads();

        #pragma unroll
        for (int kk = 0; kk < 8; kk++) {
            float4 a0 = *(const float4*)&As[kk][ty << 2];
            float4 a1 = *(const float4*)&As[kk][64 + (ty << 2)];
            float4 b0 = *(const float4*)&Bs[kk][tx << 2];
            float4 b1 = *(const float4*)&Bs[kk][64 + (tx << 2)];
            float a8[8] = {a0.x, a0.y, a0.z, a0.w, a1.x, a1.y, a1.z, a1.w};
            float b8[8] = {b0.x, b0.y, b0.z, b0.w, b1.x, b1.y, b1.z, b1.w};
            #pragma unroll
            for (int i = 0; i < 8; i++)
                #pragma unroll
                for (int j = 0; j < 8; j++)
                    acc[i][j] += a8[i] * b8[j];
        }
        __syncthreads();
    }

    #pragma unroll
    for (int i = 0; i < 8; i++) {
        int m = m0 + ((i < 4) ? ((ty << 2) + i) : (64 + (ty << 2) + i - 4));
        int b = m >> 10, n = m & 1023;
        #pragma unroll
        for (int j = 0; j < 8; j++) {
            int o = n0 + ((j < 4) ? ((tx << 2) + j) : (64 + (tx << 2) + j - 4));
            if (o < NCOLS) {
                float val = acc[i][j] + bias[o];
                if (!SCATTER) {
                    g_tokens[(size_t)m * NCOLS + o] = val;
                } else {
                    int sgrp = o / CDIM;          // 0=q 1=k 2=v
                    int cc   = o - sgrp * CDIM;
                    int h    = cc / HD;
                    int d    = cc - h * HD;
                    size_t off = ((size_t)(b * NH + h) * HD + d) * NTOK + n;
                    if (sgrp == 0)      g_qT[off] = val;
                    else if (sgrp == 1) g_kT[off] = val;
                    else                g_vT[off] = val;
                }
            }
        }
    }
}

// ---------------------------------------------------------------------------
// Flash attention per (b,h). BR=64 rows per CTA, 16 KV tiles of 64 cols.
//   Qs[d][r]  stride 64      (broadcast float4 reads)
//   KP[*][KSTR]: phase 1 = K[d][c]; phase 2 = P[r][c]
//   Vt[48][KSTR]: V[d][c], rows 42..47 zero
// Thread (ty=tid>>4, tx=tid&15) owns rows 4ty..4ty+3 in BOTH phases;
// QK cols = 4tx..4tx+3; PV dims = 3tx..3tx+2. Stats stay in registers.
// ---------------------------------------------------------------------------
__global__ __launch_bounds__(256) void attn_k(float* __restrict__ out) {
    __shared__ float Qs[HD * 64];
    __shared__ float KP[64 * KSTR];
    __shared__ float Vt[48 * KSTR];

    int tid = threadIdx.x;
    int ty = tid >> 4, tx = tid & 15;
    int bh = blockIdx.y;
    int r0 = blockIdx.x << 6;

    const float* qb = g_qT + (size_t)bh * HD * NTOK + r0;
    const float* kb = g_kT + (size_t)bh * HD * NTOK;
    const float* vb = g_vT + (size_t)bh * HD * NTOK;

    for (int idx = tid; idx < HD * 64; idx += 256) {
        int d = idx >> 6, r = idx & 63;
        Qs[idx] = qb[(size_t)d * NTOK + r];
    }
    for (int idx = tid; idx < 6 * KSTR; idx += 256)
        Vt[42 * KSTR + idx] = 0.f;              // pad rows, never rewritten

    float m_run[4], l_run[4], o_acc[4][3];
    #pragma unroll
    for (int i = 0; i < 4; i++) {
        m_run[i] = -1e30f;
        l_run[i] = 0.f;
        o_acc[i][0] = o_acc[i][1] = o_acc[i][2] = 0.f;
    }

    for (int c0 = 0; c0 < NTOK; c0 += 64) {
        for (int idx = tid; idx < HD * 64; idx += 256) {
            int d = idx >> 6, c = idx & 63;
            KP[d * KSTR + c] = kb[(size_t)d * NTOK + c0 + c];
            Vt[d * KSTR + c] = vb[(size_t)d * NTOK + c0 + c];
        }
        __syncthreads();

        // S = Q K^T  (rows 4ty.., cols 4tx..)
        float s[4][4] = {};
        #pragma unroll
        for (int d = 0; d < HD; d++) {
            float4 a = *(const float4*)&Qs[d * 64 + (ty << 2)];
            float4 b = *(const float4*)&KP[d * KSTR + (tx << 2)];
            float a4[4] = {a.x, a.y, a.z, a.w};
            float b4[4] = {b.x, b.y, b.z, b.w};
            #pragma unroll
            for (int i = 0; i < 4; i++)
                #pragma unroll
                for (int j = 0; j < 4; j++)
                    s[i][j] += a4[i] * b4[j];
        }
        __syncthreads();   // done reading KP as K

        // online softmax over 16 tx lanes; P stored row-major stride KSTR
        #pragma unroll
        for (int i = 0; i < 4; i++) {
            float mt = -1e30f;
            #pragma unroll
            for (int j = 0; j < 4; j++) {
                s[i][j] *= ATTN_SCALE;
                mt = fmaxf(mt, s[i][j]);
            }
            #pragma unroll
            for (int off = 1; off < 16; off <<= 1)
                mt = fmaxf(mt, __shfl_xor_sync(0xffffffffu, mt, off));
            float m_new = fmaxf(m_run[i], mt);
            float lt = 0.f;
            #pragma unroll
            for (int j = 0; j < 4; j++) {
                s[i][j] = __expf(s[i][j] - m_new);
                lt += s[i][j];
            }
            #pragma unroll
            for (int off = 1; off < 16; off <<= 1)
                lt += __shfl_xor_sync(0xffffffffu, lt, off);
            float alpha = __expf(m_run[i] - m_new);
            m_run[i] = m_new;
            l_run[i] = l_run[i] * alpha + lt;
            o_acc[i][0] *= alpha; o_acc[i][1] *= alpha; o_acc[i][2] *= alpha;
            *(float4*)&KP[((ty << 2) + i) * KSTR + (tx << 2)] =
                make_float4(s[i][0], s[i][1], s[i][2], s[i][3]);
        }
        __syncthreads();

        // O += P V : P rows broadcast float4, V rows (3tx+j) conflict-free
        #pragma unroll 4
        for (int cc = 0; cc < 64; cc += 4) {
            float4 v0 = *(const float4*)&Vt[(tx * 3 + 0) * KSTR + cc];
            float4 v1 = *(const float4*)&Vt[(tx * 3 + 1) * KSTR + cc];
            float4 v2 = *(const float4*)&Vt[(tx * 3 + 2) * KSTR + cc];
            #pragma unroll
            for (int i = 0; i < 4; i++) {
                float4 p = *(const float4*)&KP[((ty << 2) + i) * KSTR + cc];
                o_acc[i][0] += p.x * v0.x + p.y * v0.y + p.z * v0.z + p.w * v0.w;
                o_acc[i][1] += p.x * v1.x + p.y * v1.y + p.z * v1.z + p.w * v1.w;
                o_acc[i][2] += p.x * v2.x + p.y * v2.y + p.z * v2.z + p.w * v2.w;
            }
        }
        __syncthreads();
    }

    int b = bh / NH, h = bh - b * NH;
    #pragma unroll
    for (int i = 0; i < 4; i++) {
        int n = r0 + (ty << 2) + i;
        float inv = 1.f / l_run[i];
        #pragma unroll
        for (int j = 0; j < 3; j++) {
            int d = tx * 3 + j;
            if (d < HD)
                out[((size_t)(b * NTOK + n)) * CDIM + h * HD + d] = o_acc[i][j] * inv;
        }
    }
}

// ---------------------------------------------------------------------------
extern "C" void kernel_launch(void* const* d_in, const int* in_sizes, int n_in,
                              void* d_out, int out_size) {
    const float* x      = (const float*)d_in[0];
    const float* conv_w = (const float*)d_in[1];
    const float* conv_b = (const float*)d_in[2];
    const float* qkv_w  = (const float*)d_in[3];
    const float* qkv_b  = (const float*)d_in[4];
    float* out = (float*)d_out;

    patch_extract_k<<<(MTOT * CDIM + 255) / 256, 256>>>(x);
    gemm_k<CDIM, false><<<dim3((CDIM + 127) / 128, MTOT / 128), 256>>>(conv_w, conv_b);
    gemm_k<QKVN, true ><<<dim3((QKVN + 127) / 128, MTOT / 128), 256>>>(qkv_w, qkv_b);
    attn_k<<<dim3(NTOK / 64, B_ * NH), 256>>>(out);
}

// round 6
// speedup vs baseline: 1.2156x; 1.1147x over previous
#include <cuda_runtime.h>
#include <cstdint>

// ---------------------------------------------------------------------------
// ViT patch-embed + QKV + attention (round 5)
//  - GEMMs: tf32 tensor-core mma.sync m16n8k8, 3x-split (~fp32 accuracy)
//  - attention: unchanged from round 4
// ---------------------------------------------------------------------------

namespace {
constexpr int B_    = 8;
constexpr int NTOK  = 1024;
constexpr int CDIM  = 588;
constexpr int NH    = 14;
constexpr int HD    = 42;
constexpr int MTOT  = B_ * NTOK;     // 8192
constexpr int QKVN  = 3 * CDIM;      // 1764
constexpr float ATTN_SCALE = 0.125f;
constexpr int KSTR  = 68;            // attn smem row stride
}

__device__ float g_patches[MTOT * CDIM];
__device__ float g_tokens [MTOT * CDIM];
__device__ float g_qT[B_ * NH * HD * NTOK];
__device__ float g_kT[B_ * NH * HD * NTOK];
__device__ float g_vT[B_ * NH * HD * NTOK];

// ---------------------------------------------------------------------------
__global__ __launch_bounds__(256) void patch_extract_k(const float* __restrict__ x) {
    int idx = blockIdx.x * 256 + threadIdx.x;
    if (idx >= MTOT * CDIM) return;
    int m = idx / CDIM;
    int k = idx - m * CDIM;
    int c  = k / 196;
    int r2 = k - c * 196;
    int i  = r2 / 14;
    int j  = r2 - i * 14;
    int b  = m >> 10;
    int sp = m & 1023;
    int py = sp >> 5;
    int px = sp & 31;
    g_patches[idx] = x[((size_t)(b * 3 + c) * 448 + py * 14 + i) * 448 + (px * 14 + j)];
}

// ---------------------------------------------------------------------------
// tf32 helpers
// ---------------------------------------------------------------------------
__device__ __forceinline__ void split_tf32(float x, uint32_t& hi, uint32_t& lo) {
    asm("cvt.rna.tf32.f32 %0, %1;" : "=r"(hi) : "f"(x));
    float r = x - __uint_as_float(hi);
    asm("cvt.rna.tf32.f32 %0, %1;" : "=r"(lo) : "f"(r));
}

__device__ __forceinline__ void mma_tf32(float* d, const uint32_t* a, const uint32_t* b) {
    asm volatile(
        "mma.sync.aligned.m16n8k8.row.col.f32.tf32.tf32.f32 "
        "{%0,%1,%2,%3}, {%4,%5,%6,%7}, {%8,%9}, {%0,%1,%2,%3};"
        : "+f"(d[0]), "+f"(d[1]), "+f"(d[2]), "+f"(d[3])
        : "r"(a[0]), "r"(a[1]), "r"(a[2]), "r"(a[3]), "r"(b[0]), "r"(b[1]));
}

// ---------------------------------------------------------------------------
// Tensor-core GEMM: C[M,NCOLS] = A[M,588] @ W[NCOLS,588]^T + bias
// Tile 128(M) x 64(N) x 16(K); 8 warps = 4(M) x 2(N); warp tile 32x32.
// smem As[k][m] stride 136, Bs[k][n] stride 72 (both ≡8 mod 32 -> the
// fragment-load lane pattern 8t+g covers all 32 banks, conflict-free).
// 3x tf32 split per fragment pair => ~fp32 accuracy.
// SCATTER=false: A=g_patches -> g_tokens; SCATTER=true: A=g_tokens -> q/k/vT.
// ---------------------------------------------------------------------------
template<int NCOLS, bool SCATTER>
__global__ __launch_bounds__(256) void gemm_mma_k(const float* __restrict__ W,
                                                  const float* __restrict__ bias) {
    constexpr int K  = CDIM;
    constexpr int BK = 16;
    __shared__ float As[BK][136];
    __shared__ float Bs[BK][72];

    const float* __restrict__ A = SCATTER ? g_tokens : g_patches;

    int tid  = threadIdx.x;
    int lane = tid & 31;
    int wid  = tid >> 5;
    int g = lane >> 2, t = lane & 3;
    int wm0 = (wid >> 1) << 5;        // 0,32,64,96
    int wn0 = (wid & 1) << 5;         // 0,32
    int m0 = blockIdx.y << 7, n0 = blockIdx.x << 6;

    int l_row = tid >> 2;             // 0..63
    int l_kq  = (tid & 3) << 2;       // 0,4,8,12

    float acc[2][4][4] = {};

    for (int k0 = 0; k0 < K; k0 += BK) {
        bool kok = (k0 + l_kq) < K;   // K%4==0: float4 fully valid or fully not
        // A tile: rows l_row and l_row+64
        #pragma unroll
        for (int h = 0; h < 2; h++) {
            int m = l_row + h * 64;
            float4 v = make_float4(0.f, 0.f, 0.f, 0.f);
            if (kok) v = *(const float4*)&A[(size_t)(m0 + m) * K + k0 + l_kq];
            As[l_kq + 0][m] = v.x; As[l_kq + 1][m] = v.y;
            As[l_kq + 2][m] = v.z; As[l_kq + 3][m] = v.w;
        }
        // B tile: row l_row
        {
            float4 v = make_float4(0.f, 0.f, 0.f, 0.f);
            if (kok && (n0 + l_row) < NCOLS)
                v = *(const float4*)&W[(size_t)(n0 + l_row) * K + k0 + l_kq];
            Bs[l_kq + 0][l_row] = v.x; Bs[l_kq + 1][l_row] = v.y;
            Bs[l_kq + 2][l_row] = v.z; Bs[l_kq + 3][l_row] = v.w;
        }
        __syncthreads();

        #pragma unroll
        for (int ks = 0; ks < 2; ks++) {
            int kb = ks << 3;
            uint32_t ahi[2][4], alo[2][4], bhi[4][2], blo[4][2];
            #pragma unroll
            for (int mi = 0; mi < 2; mi++) {
                int mb = wm0 + 16 * mi + g;
                split_tf32(As[kb + t    ][mb    ], ahi[mi][0], alo[mi][0]);
                split_tf32(As[kb + t    ][mb + 8], ahi[mi][1], alo[mi][1]);
                split_tf32(As[kb + t + 4][mb    ], ahi[mi][2], alo[mi][2]);
                split_tf32(As[kb + t + 4][mb + 8], ahi[mi][3], alo[mi][3]);
            }
            #pragma unroll
            for (int ni = 0; ni < 4; ni++) {
                int nb = wn0 + 8 * ni + g;
                split_tf32(Bs[kb + t    ][nb], bhi[ni][0], blo[ni][0]);
                split_tf32(Bs[kb + t + 4][nb], bhi[ni][1], blo[ni][1]);
            }
            #pragma unroll
            for (int mi = 0; mi < 2; mi++)
                #pragma unroll
                for (int ni = 0; ni < 4; ni++) {
                    mma_tf32(acc[mi][ni], alo[mi], bhi[ni]);
                    mma_tf32(acc[mi][ni], ahi[mi], blo[ni]);
                    mma_tf32(acc[mi][ni], ahi[mi], bhi[ni]);
                }
        }
        __syncthreads();
    }

    // epilogue: c0:(g,2t) c1:(g,2t+1) c2:(g+8,2t) c3:(g+8,2t+1)
    #pragma unroll
    for (int mi = 0; mi < 2; mi++) {
        #pragma unroll
        for (int ci = 0; ci < 4; ci++) {
            int m = m0 + wm0 + 16 * mi + g + ((ci >= 2) ? 8 : 0);
            int b = m >> 10, n = m & 1023;
            #pragma unroll
            for (int ni = 0; ni < 4; ni++) {
                int o = n0 + wn0 + 8 * ni + 2 * t + (ci & 1);
                if (o < NCOLS) {
                    float val = acc[mi][ni][ci] + bias[o];
                    if (!SCATTER) {
                        g_tokens[(size_t)m * NCOLS + o] = val;
                    } else {
                        int sgrp = o / CDIM;
                        int cc   = o - sgrp * CDIM;
                        int h    = cc / HD;
                        int d    = cc - h * HD;
                        size_t off = ((size_t)(b * NH + h) * HD + d) * NTOK + n;
                        if (sgrp == 0)      g_qT[off] = val;
                        else if (sgrp == 1) g_kT[off] = val;
                        else                g_vT[off] = val;
                    }
                }
            }
        }
    }
}

// ---------------------------------------------------------------------------
// Flash attention per (b,h)  (unchanged from round 4)
// ---------------------------------------------------------------------------
__global__ __launch_bounds__(256) void attn_k(float* __restrict__ out) {
    __shared__ float Qs[HD * 64];
    __shared__ float KP[64 * KSTR];
    __shared__ float Vt[48 * KSTR];

    int tid = threadIdx.x;
    int ty = tid >> 4, tx = tid & 15;
    int bh = blockIdx.y;
    int r0 = blockIdx.x << 6;

    const float* qb = g_qT + (size_t)bh * HD * NTOK + r0;
    const float* kb = g_kT + (size_t)bh * HD * NTOK;
    const float* vb = g_vT + (size_t)bh * HD * NTOK;

    for (int idx = tid; idx < HD * 64; idx += 256) {
        int d = idx >> 6, r = idx & 63;
        Qs[idx] = qb[(size_t)d * NTOK + r];
    }
    for (int idx = tid; idx < 6 * KSTR; idx += 256)
        Vt[42 * KSTR + idx] = 0.f;

    float m_run[4], l_run[4], o_acc[4][3];
    #pragma unroll
    for (int i = 0; i < 4; i++) {
        m_run[i] = -1e30f;
        l_run[i] = 0.f;
        o_acc[i][0] = o_acc[i][1] = o_acc[i][2] = 0.f;
    }

    for (int c0 = 0; c0 < NTOK; c0 += 64) {
        for (int idx = tid; idx < HD * 64; idx += 256) {
            int d = idx >> 6, c = idx & 63;
            KP[d * KSTR + c] = kb[(size_t)d * NTOK + c0 + c];
            Vt[d * KSTR + c] = vb[(size_t)d * NTOK + c0 + c];
        }
        __syncthreads();

        float s[4][4] = {};
        #pragma unroll
        for (int d = 0; d < HD; d++) {
            float4 a = *(const float4*)&Qs[d * 64 + (ty << 2)];
            float4 b = *(const float4*)&KP[d * KSTR + (tx << 2)];
            float a4[4] = {a.x, a.y, a.z, a.w};
            float b4[4] = {b.x, b.y, b.z, b.w};
            #pragma unroll
            for (int i = 0; i < 4; i++)
                #pragma unroll
                for (int j = 0; j < 4; j++)
                    s[i][j] += a4[i] * b4[j];
        }
        __syncthreads();

        #pragma unroll
        for (int i = 0; i < 4; i++) {
            float mt = -1e30f;
            #pragma unroll
            for (int j = 0; j < 4; j++) {
                s[i][j] *= ATTN_SCALE;
                mt = fmaxf(mt, s[i][j]);
            }
            #pragma unroll
            for (int off = 1; off < 16; off <<= 1)
                mt = fmaxf(mt, __shfl_xor_sync(0xffffffffu, mt, off));
            float m_new = fmaxf(m_run[i], mt);
            float lt = 0.f;
            #pragma unroll
            for (int j = 0; j < 4; j++) {
                s[i][j] = __expf(s[i][j] - m_new);
                lt += s[i][j];
            }
            #pragma unroll
            for (int off = 1; off < 16; off <<= 1)
                lt += __shfl_xor_sync(0xffffffffu, lt, off);
            float alpha = __expf(m_run[i] - m_new);
            m_run[i] = m_new;
            l_run[i] = l_run[i] * alpha + lt;
            o_acc[i][0] *= alpha; o_acc[i][1] *= alpha; o_acc[i][2] *= alpha;
            *(float4*)&KP[((ty << 2) + i) * KSTR + (tx << 2)] =
                make_float4(s[i][0], s[i][1], s[i][2], s[i][3]);
        }
        __syncthreads();

        #pragma unroll 4
        for (int cc = 0; cc < 64; cc += 4) {
            float4 v0 = *(const float4*)&Vt[(tx * 3 + 0) * KSTR + cc];
            float4 v1 = *(const float4*)&Vt[(tx * 3 + 1) * KSTR + cc];
            float4 v2 = *(const float4*)&Vt[(tx * 3 + 2) * KSTR + cc];
            #pragma unroll
            for (int i = 0; i < 4; i++) {
                float4 p = *(const float4*)&KP[((ty << 2) + i) * KSTR + cc];
                o_acc[i][0] += p.x * v0.x + p.y * v0.y + p.z * v0.z + p.w * v0.w;
                o_acc[i][1] += p.x * v1.x + p.y * v1.y + p.z * v1.z + p.w * v1.w;
                o_acc[i][2] += p.x * v2.x + p.y * v2.y + p.z * v2.z + p.w * v2.w;
            }
        }
        __syncthreads();
    }

    int b = bh / NH, h = bh - b * NH;
    #pragma unroll
    for (int i = 0; i < 4; i++) {
        int n = r0 + (ty << 2) + i;
        float inv = 1.f / l_run[i];
        #pragma unroll
        for (int j = 0; j < 3; j++) {
            int d = tx * 3 + j;
            if (d < HD)
                out[((size_t)(b * NTOK + n)) * CDIM + h * HD + d] = o_acc[i][j] * inv;
        }
    }
}

// ---------------------------------------------------------------------------
extern "C" void kernel_launch(void* const* d_in, const int* in_sizes, int n_in,
                              void* d_out, int out_size) {
    const float* x      = (const float*)d_in[0];
    const float* conv_w = (const float*)d_in[1];
    const float* conv_b = (const float*)d_in[2];
    const float* qkv_w  = (const float*)d_in[3];
    const float* qkv_b  = (const float*)d_in[4];
    float* out = (float*)d_out;

    patch_extract_k<<<(MTOT * CDIM + 255) / 256, 256>>>(x);
    gemm_mma_k<CDIM, false><<<dim3((CDIM + 63) / 64, MTOT / 128), 256>>>(conv_w, conv_b);
    gemm_mma_k<QKVN, true ><<<dim3((QKVN + 63) / 64, MTOT / 128), 256>>>(qkv_w, qkv_b);
    attn_k<<<dim3(NTOK / 64, B_ * NH), 256>>>(out);
}